// round 9
// baseline (speedup 1.0000x reference)
#include <cuda_runtime.h>

// HandGraphConvNet fused: 2-layer GCN + BN(eval) + relu + residual, fp32.
//   Y  = A @ X            (sparse A: <=6 nnz/row, fixed hand-skeleton pattern)
//   H  = relu(Y @ W1' + beta1')      (never materialized)
//   S2 = H @ W2'
//   out = A @ S2 + beta2' + x
// Persistent-block pipeline: 148 blocks x 672 threads (warp <-> joint,
// lane <-> sample). Each block owns ~3.46 chunks of 64 samples and double-
// buffers chunk X via cp.async so DRAM latency overlaps compute. Constants
// are folded once per block (not once per 64 samples as before).

#define NJ 21
#define HDIM 42
#define HIDDEN 64
#define CHUNK 64               // samples per chunk (2 per lane)
#define NTHREADS 672           // 21 warps
#define NBLOCKS 148
#define BN_EPS 1e-5f

typedef unsigned long long ull;

__constant__ int c_nbr[NJ * 6] = {
    0,1,5,9,13,17,
    0,1,2,0,0,0, 1,2,3,0,0,0, 2,3,4,0,0,0, 3,4,0,0,0,0,
    0,5,6,0,0,0, 5,6,7,0,0,0, 6,7,8,0,0,0, 7,8,0,0,0,0,
    0,9,10,0,0,0, 9,10,11,0,0,0, 10,11,12,0,0,0, 11,12,0,0,0,0,
    0,13,14,0,0,0, 13,14,15,0,0,0, 14,15,16,0,0,0, 15,16,0,0,0,0,
    0,17,18,0,0,0, 17,18,19,0,0,0, 18,19,20,0,0,0, 19,20,0,0,0,0};
__constant__ int c_cnt[NJ] = {6,3,3,3,2,3,3,3,2,3,3,3,2,3,3,3,2,3,3,3,2};

__device__ __forceinline__ ull pk2(float lo, float hi) {
    ull r; asm("mov.b64 %0, {%1, %2};" : "=l"(r) : "f"(lo), "f"(hi)); return r;
}
__device__ __forceinline__ void upk2(ull v, float& lo, float& hi) {
    asm("mov.b64 {%0, %1}, %2;" : "=f"(lo), "=f"(hi) : "l"(v));
}
__device__ __forceinline__ ull ffma2(ull a, ull b, ull c) {
    ull d; asm("fma.rn.f32x2 %0, %1, %2, %3;" : "=l"(d) : "l"(a), "l"(b), "l"(c)); return d;
}
__device__ __forceinline__ ull fadd2(ull a, ull b) {
    ull d; asm("add.rn.f32x2 %0, %1, %2;" : "=l"(d) : "l"(a), "l"(b)); return d;
}
__device__ __forceinline__ void cp_async16(unsigned int dst, const void* src) {
    asm volatile("cp.async.cg.shared.global [%0], [%1], 16;" :: "r"(dst), "l"(src));
}

__global__ __launch_bounds__(NTHREADS, 1)
void hand_gcn_kernel(const float* __restrict__ x,  const float* __restrict__ adj,
                     const float* __restrict__ W1, const float* __restrict__ b1,
                     const float* __restrict__ W2, const float* __restrict__ b2,
                     const float* __restrict__ g1, const float* __restrict__ be1,
                     const float* __restrict__ m1, const float* __restrict__ v1,
                     const float* __restrict__ g2, const float* __restrict__ be2,
                     const float* __restrict__ m2, const float* __restrict__ v2,
                     float* __restrict__ out, int nsamples)
{
    // lane word-stride 42 mod 32 = 10 -> 64-bit accesses conflict-free
    __shared__ alignas(16) float xs2[2][CHUNK * HDIM];  // double-buffered X
    __shared__ alignas(16) float s2s[CHUNK * HDIM];     // S2 scratch
    __shared__ alignas(16) ulonglong2 cap[32];  // packed W1' column pair
    __shared__ alignas(16) ulonglong2 cbp[32];  // packed W2' row pair
    __shared__ ull ccp[32];                     // packed beta1' pair
    __shared__ ull adjp[NJ * 6];                // packed (a,a)
    __shared__ ull beta2p;

    const int tid  = threadIdx.x;
    const int w    = tid >> 5;           // warp <-> joint
    const int lane = tid & 31;
    const long long total = (long long)nsamples * HDIM;

    // ---- chunk range for this block (near-even split) ----
    const int total_chunks = (nsamples + CHUNK - 1) / CHUNK;
    const int start = (int)((long long)blockIdx.x       * total_chunks / NBLOCKS);
    const int end   = (int)((long long)(blockIdx.x + 1) * total_chunks / NBLOCKS);
    const int nchunks = end - start;

    // smem byte addresses for cp.async destinations
    unsigned int xs2_base[2];
    xs2_base[0] = (unsigned int)__cvta_generic_to_shared(&xs2[0][0]) + tid * 16;
    xs2_base[1] = (unsigned int)__cvta_generic_to_shared(&xs2[1][0]) + tid * 16;

    // ---- prefetch chunk 0 (and 1) ----
    if (nchunks > 0) {
        long long g = (long long)start * (CHUNK * HDIM) + 4LL * tid;
        if (g + 4 <= total) cp_async16(xs2_base[0], x + g);
        else { float4 z = make_float4(0,0,0,0); *(float4*)(&xs2[0][4*tid]) = z; }
    }
    asm volatile("cp.async.commit_group;");
    if (nchunks > 1) {
        long long g = (long long)(start + 1) * (CHUNK * HDIM) + 4LL * tid;
        if (g + 4 <= total) cp_async16(xs2_base[1], x + g);
        else { float4 z = make_float4(0,0,0,0); *(float4*)(&xs2[1][4*tid]) = z; }
    }
    asm volatile("cp.async.commit_group;");

    // ---- fold BN into pre-packed constants (once per block) ----
    if (tid < 32) {
        int c0 = 2 * tid, c1 = c0 + 1;
        float al0 = g1[c0] * rsqrtf(v1[c0] + BN_EPS);
        float al1 = g1[c1] * rsqrtf(v1[c1] + BN_EPS);
        cap[tid] = make_ulonglong2(pk2(W1[c0] * al0, W1[c1] * al1),
                                   pk2(W1[HIDDEN + c0] * al0, W1[HIDDEN + c1] * al1));
        ccp[tid] = pk2((b1[c0] - m1[c0]) * al0 + be1[c0],
                       (b1[c1] - m1[c1]) * al1 + be1[c1]);
        float a20 = g2[0] * rsqrtf(v2[0] + BN_EPS);
        float a21 = g2[1] * rsqrtf(v2[1] + BN_EPS);
        cbp[tid] = make_ulonglong2(pk2(W2[c0 * 2] * a20, W2[c1 * 2] * a20),
                                   pk2(W2[c0 * 2 + 1] * a21, W2[c1 * 2 + 1] * a21));
        if (tid == 0)
            beta2p = pk2((b2[0] - m2[0]) * a20 + be2[0],
                         (b2[1] - m2[1]) * a21 + be2[1]);
    }
    if (tid >= 64 && tid < 64 + NJ * 6) {
        int i = tid - 64;
        int jj = i / 6, ii = i % 6;
        float a = (ii < c_cnt[jj]) ? adj[jj * NJ + c_nbr[i]] : 0.f;
        adjp[i] = pk2(a, a);
    }

    // ---- main chunk loop, 2-stage pipeline ----
    for (int i = 0; i < nchunks; ++i) {
        const int buf = i & 1;
        // wait for chunk i (leave next in flight unless this is the last)
        if (i == nchunks - 1) asm volatile("cp.async.wait_group 0;");
        else                  asm volatile("cp.async.wait_group 1;");
        __syncthreads();     // X(i) visible to all; also covers constants on i==0

        const float* __restrict__ cx = &xs2[buf][0];
        const long long base = (long long)(start + i) * (CHUNK * HDIM);

        // -- Y = (A@X)[w] for 2 samples (lane, lane+32) --
        ull y0d[2], y1d[2];
        #pragma unroll
        for (int k = 0; k < 2; ++k) {
            const float* xr = cx + (lane + 32 * k) * HDIM;
            ull y = 0ULL;
            #pragma unroll
            for (int q = 0; q < 6; ++q)
                y = ffma2(adjp[w * 6 + q], *(const ull*)(xr + 2 * c_nbr[w * 6 + q]), y);
            float y0, y1; upk2(y, y0, y1);
            y0d[k] = pk2(y0, y0);
            y1d[k] = pk2(y1, y1);
        }

        // -- fused layer1 (+BN+relu) -> layer2 contraction --
        ull a0[2] = {0ULL, 0ULL}, a1[2] = {0ULL, 0ULL};
        #pragma unroll
        for (int cp = 0; cp < 32; ++cp) {
            ulonglong2 wa = cap[cp];
            ull        bp = ccp[cp];
            ulonglong2 wb = cbp[cp];
            #pragma unroll
            for (int k = 0; k < 2; ++k) {
                ull h = ffma2(y0d[k], wa.x, ffma2(y1d[k], wa.y, bp));
                float hl, hh; upk2(h, hl, hh);
                h = pk2(fmaxf(hl, 0.f), fmaxf(hh, 0.f));
                a0[k] = ffma2(h, wb.x, a0[k]);
                a1[k] = ffma2(h, wb.y, a1[k]);
            }
        }
        #pragma unroll
        for (int k = 0; k < 2; ++k) {
            float p, q, r, s;
            upk2(a0[k], p, q);
            upk2(a1[k], r, s);
            *(float2*)(s2s + (lane + 32 * k) * HDIM + 2 * w) = make_float2(p + q, r + s);
        }
        __syncthreads();   // S2 complete

        // -- out = A @ S2 + beta2' + x, direct scattered STG.64 --
        const ull b2pk = beta2p;
        #pragma unroll
        for (int k = 0; k < 2; ++k) {
            const int row = (lane + 32 * k) * HDIM;
            const float* sr = s2s + row;
            ull o = b2pk;
            #pragma unroll
            for (int q = 0; q < 6; ++q)
                o = ffma2(adjp[w * 6 + q], *(const ull*)(sr + 2 * c_nbr[w * 6 + q]), o);
            o = fadd2(o, *(const ull*)(cx + row + 2 * w));
            long long g = base + row + 2 * w;
            if (g < total) {
                float o0, o1; upk2(o, o0, o1);
                *(float2*)(out + g) = make_float2(o0, o1);
            }
        }
        __syncthreads();   // buf + s2s free for reuse

        // -- prefetch chunk i+2 into this buffer --
        if (i + 2 < nchunks) {
            long long g = (long long)(start + i + 2) * (CHUNK * HDIM) + 4LL * tid;
            if (g + 4 <= total) cp_async16(xs2_base[buf], x + g);
            else { float4 z = make_float4(0,0,0,0); *(float4*)(&xs2[buf][4*tid]) = z; }
        }
        asm volatile("cp.async.commit_group;");
    }
}

extern "C" void kernel_launch(void* const* d_in, const int* in_sizes, int n_in,
                              void* d_out, int out_size) {
    int nsamples = in_sizes[0] / HDIM;
    hand_gcn_kernel<<<NBLOCKS, NTHREADS>>>(
        (const float*)d_in[0],  (const float*)d_in[1],  (const float*)d_in[2],
        (const float*)d_in[3],  (const float*)d_in[4],  (const float*)d_in[5],
        (const float*)d_in[6],  (const float*)d_in[7],  (const float*)d_in[8],
        (const float*)d_in[9],  (const float*)d_in[10], (const float*)d_in[11],
        (const float*)d_in[12], (const float*)d_in[13],
        (float*)d_out, nsamples);
}

// round 12
// speedup vs baseline: 1.0282x; 1.0282x over previous
#include <cuda_runtime.h>

// HandGraphConvNet fused: 2-layer GCN + BN(eval) + relu + residual, fp32.
//   Y  = A @ X            (sparse A: wrist=6 nnz, all other joints <=3)
//   H  = relu(Y @ W1' + beta1')      (never materialized)
//   S2 = H @ W2'
//   out = A @ S2 + beta2' + x
// Mapping: block = 7 warps; warp w <-> joints {3w..3w+2}, lane <-> sample,
// 2 samples/thread => 6 (sample,joint) units amortize each constant load.
// R10: aggregation unrolled to actual nnz (6 only for wrist, else 3).

#define NJ 21
#define HDIM 42
#define HIDDEN 64
#define SPB 64                 // samples per block (2 per lane)
#define NTHREADS 224           // 7 warps
#define BN_EPS 1e-5f

typedef unsigned long long ull;

__constant__ int c_nbr[NJ * 6] = {
    0,1,5,9,13,17,
    0,1,2,0,0,0, 1,2,3,0,0,0, 2,3,4,0,0,0, 3,4,0,0,0,0,
    0,5,6,0,0,0, 5,6,7,0,0,0, 6,7,8,0,0,0, 7,8,0,0,0,0,
    0,9,10,0,0,0, 9,10,11,0,0,0, 10,11,12,0,0,0, 11,12,0,0,0,0,
    0,13,14,0,0,0, 13,14,15,0,0,0, 14,15,16,0,0,0, 15,16,0,0,0,0,
    0,17,18,0,0,0, 17,18,19,0,0,0, 18,19,20,0,0,0, 19,20,0,0,0,0};
__constant__ int c_cnt[NJ] = {6,3,3,3,2,3,3,3,2,3,3,3,2,3,3,3,2,3,3,3,2};

__device__ __forceinline__ ull pk2(float lo, float hi) {
    ull r; asm("mov.b64 %0, {%1, %2};" : "=l"(r) : "f"(lo), "f"(hi)); return r;
}
__device__ __forceinline__ void upk2(ull v, float& lo, float& hi) {
    asm("mov.b64 {%0, %1}, %2;" : "=f"(lo), "=f"(hi) : "l"(v));
}
__device__ __forceinline__ ull ffma2(ull a, ull b, ull c) {
    ull d; asm("fma.rn.f32x2 %0, %1, %2, %3;" : "=l"(d) : "l"(a), "l"(b), "l"(c)); return d;
}
__device__ __forceinline__ ull fadd2(ull a, ull b) {
    ull d; asm("add.rn.f32x2 %0, %1, %2;" : "=l"(d) : "l"(a), "l"(b)); return d;
}

__global__ __launch_bounds__(NTHREADS, 3)
void hand_gcn_kernel(const float* __restrict__ x,  const float* __restrict__ adj,
                     const float* __restrict__ W1, const float* __restrict__ b1,
                     const float* __restrict__ W2, const float* __restrict__ b2,
                     const float* __restrict__ g1, const float* __restrict__ be1,
                     const float* __restrict__ m1, const float* __restrict__ v1,
                     const float* __restrict__ g2, const float* __restrict__ be2,
                     const float* __restrict__ m2, const float* __restrict__ v2,
                     float* __restrict__ out, int nsamples)
{
    // lane word-stride 42 (10 mod 32) -> LDS.64 conflict-free per phase
    __shared__ alignas(16) float xs [SPB * HDIM];   // staged X (kept intact)
    __shared__ alignas(16) float s2s[SPB * HDIM];   // S2 scratch
    __shared__ alignas(16) ulonglong2 cap[32];  // packed W1' column pair
    __shared__ alignas(16) ulonglong2 cbp[32];  // packed W2' row pair
    __shared__ ull ccp[32];                     // packed beta1' pair
    __shared__ ull adjp[NJ * 6];                // packed (a,a)
    __shared__ ull beta2p;

    const int tid  = threadIdx.x;
    const int w    = tid >> 5;          // warp -> joint triple
    const int lane = tid & 31;          // sample slot
    const long long base  = (long long)blockIdx.x * (SPB * HDIM);
    const long long total = (long long)nsamples * HDIM;

    // ---- stage X: 672 float4 = exactly 3 per thread ----
    float4* xs4 = (float4*)xs;
    #pragma unroll
    for (int i = tid; i < SPB * HDIM / 4; i += NTHREADS) {
        long long g = base + 4LL * i;
        float4 v = make_float4(0.f, 0.f, 0.f, 0.f);
        if (g < total) v = *(const float4*)(x + g);
        xs4[i] = v;
    }

    // ---- fold BN into pre-packed weight/bias constants ----
    if (tid < 32) {
        int c0 = 2 * tid, c1 = c0 + 1;
        float al0 = g1[c0] * rsqrtf(v1[c0] + BN_EPS);
        float al1 = g1[c1] * rsqrtf(v1[c1] + BN_EPS);
        cap[tid] = make_ulonglong2(pk2(W1[c0] * al0, W1[c1] * al1),
                                   pk2(W1[HIDDEN + c0] * al0, W1[HIDDEN + c1] * al1));
        ccp[tid] = pk2((b1[c0] - m1[c0]) * al0 + be1[c0],
                       (b1[c1] - m1[c1]) * al1 + be1[c1]);
        float a20 = g2[0] * rsqrtf(v2[0] + BN_EPS);
        float a21 = g2[1] * rsqrtf(v2[1] + BN_EPS);
        cbp[tid] = make_ulonglong2(pk2(W2[c0 * 2] * a20, W2[c1 * 2] * a20),
                                   pk2(W2[c0 * 2 + 1] * a21, W2[c1 * 2 + 1] * a21));
        if (tid == 0)
            beta2p = pk2((b2[0] - m2[0]) * a20 + be2[0],
                         (b2[1] - m2[1]) * a21 + be2[1]);
    }
    if (tid >= 64 && tid < 64 + NJ * 6) {
        int i = tid - 64;
        int jj = i / 6, ii = i % 6;
        float a = (ii < c_cnt[jj]) ? adj[jj * NJ + c_nbr[i]] : 0.f;
        adjp[i] = pk2(a, a);
    }
    __syncthreads();

    // ---- Y = (A@X)[j] for 2 samples x 3 joints, splat halves ----
    // wrist (warp 0, jj 0) has 6 nnz; every other joint <=3 (zero-padded)
    ull y0d[6], y1d[6];
    #pragma unroll
    for (int k = 0; k < 2; ++k) {
        const float* xr = xs + (lane + 32 * k) * HDIM;
        #pragma unroll
        for (int jj = 0; jj < 3; ++jj) {
            const int j = 3 * w + jj;
            ull y = 0ULL;
            if (jj == 0 && w == 0) {           // wrist: 6 neighbors
                #pragma unroll
                for (int q = 0; q < 6; ++q)
                    y = ffma2(adjp[q], *(const ull*)(xr + 2 * c_nbr[q]), y);
            } else {                            // finger joints: <=3 neighbors
                #pragma unroll
                for (int q = 0; q < 3; ++q)
                    y = ffma2(adjp[j * 6 + q], *(const ull*)(xr + 2 * c_nbr[j * 6 + q]), y);
            }
            float y0, y1; upk2(y, y0, y1);
            y0d[k * 3 + jj] = pk2(y0, y0);
            y1d[k * 3 + jj] = pk2(y1, y1);
        }
    }

    // ---- fused layer1 (+BN+relu) -> layer2 contraction, 6 units/thread ----
    ull a0[6], a1[6];
    #pragma unroll
    for (int t = 0; t < 6; ++t) { a0[t] = 0ULL; a1[t] = 0ULL; }
    #pragma unroll
    for (int cp = 0; cp < 32; ++cp) {
        ulonglong2 wa = cap[cp];      // LDS.128 broadcast
        ull        bp = ccp[cp];      // LDS.64
        ulonglong2 wb = cbp[cp];      // LDS.128
        #pragma unroll
        for (int t = 0; t < 6; ++t) {
            ull h = ffma2(y0d[t], wa.x, ffma2(y1d[t], wa.y, bp));
            float hl, hh; upk2(h, hl, hh);
            h = pk2(fmaxf(hl, 0.f), fmaxf(hh, 0.f));
            a0[t] = ffma2(h, wb.x, a0[t]);
            a1[t] = ffma2(h, wb.y, a1[t]);
        }
    }
    #pragma unroll
    for (int k = 0; k < 2; ++k)
        #pragma unroll
        for (int jj = 0; jj < 3; ++jj) {
            const int t = k * 3 + jj;
            float p, q, r, s;
            upk2(a0[t], p, q);
            upk2(a1[t], r, s);
            *(float2*)(s2s + (lane + 32 * k) * HDIM + 2 * (3 * w + jj)) =
                make_float2(p + q, r + s);
        }
    __syncthreads();   // S2 complete (xs untouched)

    // ---- out = A @ S2 + beta2' + x, direct scattered STG.64 ----
    const ull b2pk = beta2p;
    #pragma unroll
    for (int k = 0; k < 2; ++k) {
        const int row = (lane + 32 * k) * HDIM;
        const float* sr = s2s + row;
        #pragma unroll
        for (int jj = 0; jj < 3; ++jj) {
            const int j = 3 * w + jj;
            ull o = b2pk;
            if (jj == 0 && w == 0) {
                #pragma unroll
                for (int q = 0; q < 6; ++q)
                    o = ffma2(adjp[q], *(const ull*)(sr + 2 * c_nbr[q]), o);
            } else {
                #pragma unroll
                for (int q = 0; q < 3; ++q)
                    o = ffma2(adjp[j * 6 + q], *(const ull*)(sr + 2 * c_nbr[j * 6 + q]), o);
            }
            o = fadd2(o, *(const ull*)(xs + row + 2 * j));
            long long g = base + row + 2 * j;
            if (g < total) {
                float o0, o1; upk2(o, o0, o1);
                *(float2*)(out + g) = make_float2(o0, o1);
            }
        }
    }
}

extern "C" void kernel_launch(void* const* d_in, const int* in_sizes, int n_in,
                              void* d_out, int out_size) {
    int nsamples = in_sizes[0] / HDIM;
    int grid = (nsamples + SPB - 1) / SPB;
    hand_gcn_kernel<<<grid, NTHREADS>>>(
        (const float*)d_in[0],  (const float*)d_in[1],  (const float*)d_in[2],
        (const float*)d_in[3],  (const float*)d_in[4],  (const float*)d_in[5],
        (const float*)d_in[6],  (const float*)d_in[7],  (const float*)d_in[8],
        (const float*)d_in[9],  (const float*)d_in[10], (const float*)d_in[11],
        (const float*)d_in[12], (const float*)d_in[13],
        (float*)d_out, nsamples);
}

// round 13
// speedup vs baseline: 1.2617x; 1.2270x over previous
#include <cuda_runtime.h>

// HandGraphConvNet fused: 2-layer GCN + BN(eval) + relu + residual, fp32.
//   Y  = A @ X            (sparse A: wrist=6 nnz, all other joints <=3)
//   H  = relu(Y @ W1' + beta1')      (never materialized)
//   S2 = H @ W2'
//   out = A @ S2 + beta2' + x
// Mapping: block = 7 warps; warp w <-> joints {3w..3w+2}, lane <-> sample,
// 2 samples/thread => 6 (sample,joint) units amortize each constant load.
// R11: branchless packed relu  relu(h)*w == (h + (h & 0x7fffffff)) * (w/2)
// (both scalings are exact powers of 2) -> no pack/unpack movs, no FMNMX.

#define NJ 21
#define HDIM 42
#define HIDDEN 64
#define SPB 64                 // samples per block (2 per lane)
#define NTHREADS 224           // 7 warps
#define BN_EPS 1e-5f

typedef unsigned long long ull;

__constant__ int c_nbr[NJ * 6] = {
    0,1,5,9,13,17,
    0,1,2,0,0,0, 1,2,3,0,0,0, 2,3,4,0,0,0, 3,4,0,0,0,0,
    0,5,6,0,0,0, 5,6,7,0,0,0, 6,7,8,0,0,0, 7,8,0,0,0,0,
    0,9,10,0,0,0, 9,10,11,0,0,0, 10,11,12,0,0,0, 11,12,0,0,0,0,
    0,13,14,0,0,0, 13,14,15,0,0,0, 14,15,16,0,0,0, 15,16,0,0,0,0,
    0,17,18,0,0,0, 17,18,19,0,0,0, 18,19,20,0,0,0, 19,20,0,0,0,0};
__constant__ int c_cnt[NJ] = {6,3,3,3,2,3,3,3,2,3,3,3,2,3,3,3,2,3,3,3,2};

__device__ __forceinline__ ull pk2(float lo, float hi) {
    ull r; asm("mov.b64 %0, {%1, %2};" : "=l"(r) : "f"(lo), "f"(hi)); return r;
}
__device__ __forceinline__ void upk2(ull v, float& lo, float& hi) {
    asm("mov.b64 {%0, %1}, %2;" : "=f"(lo), "=f"(hi) : "l"(v));
}
__device__ __forceinline__ ull ffma2(ull a, ull b, ull c) {
    ull d; asm("fma.rn.f32x2 %0, %1, %2, %3;" : "=l"(d) : "l"(a), "l"(b), "l"(c)); return d;
}
__device__ __forceinline__ ull fadd2(ull a, ull b) {
    ull d; asm("add.rn.f32x2 %0, %1, %2;" : "=l"(d) : "l"(a), "l"(b)); return d;
}

__global__ __launch_bounds__(NTHREADS, 3)
void hand_gcn_kernel(const float* __restrict__ x,  const float* __restrict__ adj,
                     const float* __restrict__ W1, const float* __restrict__ b1,
                     const float* __restrict__ W2, const float* __restrict__ b2,
                     const float* __restrict__ g1, const float* __restrict__ be1,
                     const float* __restrict__ m1, const float* __restrict__ v1,
                     const float* __restrict__ g2, const float* __restrict__ be2,
                     const float* __restrict__ m2, const float* __restrict__ v2,
                     float* __restrict__ out, int nsamples)
{
    // lane word-stride 42 (10 mod 32) -> LDS.64 conflict-free per phase
    __shared__ alignas(16) float xs [SPB * HDIM];   // staged X (kept intact)
    __shared__ alignas(16) float s2s[SPB * HDIM];   // S2 scratch
    __shared__ alignas(16) ulonglong2 cap[32];  // packed W1' column pair
    __shared__ alignas(16) ulonglong2 cbp[32];  // packed (W2'/2) row pair
    __shared__ ull ccp[32];                     // packed beta1' pair
    __shared__ ull adjp[NJ * 6];                // packed (a,a)
    __shared__ ull beta2p;

    const int tid  = threadIdx.x;
    const int w    = tid >> 5;          // warp -> joint triple
    const int lane = tid & 31;          // sample slot
    const long long base  = (long long)blockIdx.x * (SPB * HDIM);
    const long long total = (long long)nsamples * HDIM;

    // ---- stage X: 672 float4 = exactly 3 per thread ----
    float4* xs4 = (float4*)xs;
    #pragma unroll
    for (int i = tid; i < SPB * HDIM / 4; i += NTHREADS) {
        long long g = base + 4LL * i;
        float4 v = make_float4(0.f, 0.f, 0.f, 0.f);
        if (g < total) v = *(const float4*)(x + g);
        xs4[i] = v;
    }

    // ---- fold BN into pre-packed weight/bias constants ----
    if (tid < 32) {
        int c0 = 2 * tid, c1 = c0 + 1;
        float al0 = g1[c0] * rsqrtf(v1[c0] + BN_EPS);
        float al1 = g1[c1] * rsqrtf(v1[c1] + BN_EPS);
        cap[tid] = make_ulonglong2(pk2(W1[c0] * al0, W1[c1] * al1),
                                   pk2(W1[HIDDEN + c0] * al0, W1[HIDDEN + c1] * al1));
        ccp[tid] = pk2((b1[c0] - m1[c0]) * al0 + be1[c0],
                       (b1[c1] - m1[c1]) * al1 + be1[c1]);
        float a20 = 0.5f * g2[0] * rsqrtf(v2[0] + BN_EPS);   // 1/2 folded for relu trick
        float a21 = 0.5f * g2[1] * rsqrtf(v2[1] + BN_EPS);
        cbp[tid] = make_ulonglong2(pk2(W2[c0 * 2] * a20, W2[c1 * 2] * a20),
                                   pk2(W2[c0 * 2 + 1] * a21, W2[c1 * 2 + 1] * a21));
        if (tid == 0) {
            float b20 = (b2[0] - m2[0]) * (2.0f * a20) + be2[0];
            float b21 = (b2[1] - m2[1]) * (2.0f * a21) + be2[1];
            beta2p = pk2(b20, b21);
        }
    }
    if (tid >= 64 && tid < 64 + NJ * 6) {
        int i = tid - 64;
        int jj = i / 6, ii = i % 6;
        float a = (ii < c_cnt[jj]) ? adj[jj * NJ + c_nbr[i]] : 0.f;
        adjp[i] = pk2(a, a);
    }
    __syncthreads();

    // ---- Y = (A@X)[j] for 2 samples x 3 joints, splat halves ----
    // wrist (warp 0, jj 0) has 6 nnz; every other joint <=3 (zero-padded)
    ull y0d[6], y1d[6];
    #pragma unroll
    for (int k = 0; k < 2; ++k) {
        const float* xr = xs + (lane + 32 * k) * HDIM;
        #pragma unroll
        for (int jj = 0; jj < 3; ++jj) {
            const int j = 3 * w + jj;
            ull y = 0ULL;
            if (jj == 0 && w == 0) {           // wrist: 6 neighbors
                #pragma unroll
                for (int q = 0; q < 6; ++q)
                    y = ffma2(adjp[q], *(const ull*)(xr + 2 * c_nbr[q]), y);
            } else {                            // finger joints: <=3 neighbors
                #pragma unroll
                for (int q = 0; q < 3; ++q)
                    y = ffma2(adjp[j * 6 + q], *(const ull*)(xr + 2 * c_nbr[j * 6 + q]), y);
            }
            float y0, y1; upk2(y, y0, y1);
            y0d[k * 3 + jj] = pk2(y0, y0);
            y1d[k * 3 + jj] = pk2(y1, y1);
        }
    }

    // ---- fused layer1 (+BN+relu) -> layer2 contraction, 6 units/thread ----
    // relu(h)*w == (h + (h & sign-clear)) * (w/2); the 1/2 is pre-folded in cbp
    const ull ABSMASK = 0x7FFFFFFF7FFFFFFFULL;
    ull a0[6], a1[6];
    #pragma unroll
    for (int t = 0; t < 6; ++t) { a0[t] = 0ULL; a1[t] = 0ULL; }
    #pragma unroll
    for (int cp = 0; cp < 32; ++cp) {
        ulonglong2 wa = cap[cp];      // LDS.128 broadcast
        ull        bp = ccp[cp];      // LDS.64
        ulonglong2 wb = cbp[cp];      // LDS.128 (pre-scaled by 1/2)
        #pragma unroll
        for (int t = 0; t < 6; ++t) {
            ull h  = ffma2(y0d[t], wa.x, ffma2(y1d[t], wa.y, bp));
            ull hr = fadd2(h, h & ABSMASK);        // 2*relu(h), packed, no movs
            a0[t] = ffma2(hr, wb.x, a0[t]);
            a1[t] = ffma2(hr, wb.y, a1[t]);
        }
    }
    #pragma unroll
    for (int k = 0; k < 2; ++k)
        #pragma unroll
        for (int jj = 0; jj < 3; ++jj) {
            const int t = k * 3 + jj;
            float p, q, r, s;
            upk2(a0[t], p, q);
            upk2(a1[t], r, s);
            *(float2*)(s2s + (lane + 32 * k) * HDIM + 2 * (3 * w + jj)) =
                make_float2(p + q, r + s);
        }
    __syncthreads();   // S2 complete (xs untouched)

    // ---- out = A @ S2 + beta2' + x, direct scattered STG.64 ----
    const ull b2pk = beta2p;
    #pragma unroll
    for (int k = 0; k < 2; ++k) {
        const int row = (lane + 32 * k) * HDIM;
        const float* sr = s2s + row;
        #pragma unroll
        for (int jj = 0; jj < 3; ++jj) {
            const int j = 3 * w + jj;
            ull o = b2pk;
            if (jj == 0 && w == 0) {
                #pragma unroll
                for (int q = 0; q < 6; ++q)
                    o = ffma2(adjp[q], *(const ull*)(sr + 2 * c_nbr[q]), o);
            } else {
                #pragma unroll
                for (int q = 0; q < 3; ++q)
                    o = ffma2(adjp[j * 6 + q], *(const ull*)(sr + 2 * c_nbr[j * 6 + q]), o);
            }
            o = fadd2(o, *(const ull*)(xs + row + 2 * j));
            long long g = base + row + 2 * j;
            if (g < total) {
                float o0, o1; upk2(o, o0, o1);
                *(float2*)(out + g) = make_float2(o0, o1);
            }
        }
    }
}

extern "C" void kernel_launch(void* const* d_in, const int* in_sizes, int n_in,
                              void* d_out, int out_size) {
    int nsamples = in_sizes[0] / HDIM;
    int grid = (nsamples + SPB - 1) / SPB;
    hand_gcn_kernel<<<grid, NTHREADS>>>(
        (const float*)d_in[0],  (const float*)d_in[1],  (const float*)d_in[2],
        (const float*)d_in[3],  (const float*)d_in[4],  (const float*)d_in[5],
        (const float*)d_in[6],  (const float*)d_in[7],  (const float*)d_in[8],
        (const float*)d_in[9],  (const float*)d_in[10], (const float*)d_in[11],
        (const float*)d_in[12], (const float*)d_in[13],
        (float*)d_out, nsamples);
}